// round 16
// baseline (speedup 1.0000x reference)
#include <cuda_runtime.h>
#include <cuda_fp16.h>
#include <math.h>
#include <stdint.h>

#define Bn    256
#define Tn    512
#define Dn    512
#define Hn    512
#define H3    1536
#define DICTn 1024
#define Qn    32
#define BT    (Bn*Tn)
#define NSAMP (Bn*Qn*DICTn)   // 8388608

#define NCTA_REC 128
#define WS_UNITS (96*256)     // W slice uint2 units (96 gh rows x 256 k-pairs)
#define INV2048  4.8828125e-4f

// ---------------- static device scratch -------------------------------------
__device__ float g_GI[(size_t)BT * H3];
__device__ float g_h[2][Bn * Hn];
__device__ float g_c1[Bn * Hn];
__device__ float g_c2[Bn * Hn];
__device__ float g_logits[(size_t)Bn * Qn * DICTn];
__device__ unsigned g_barrier[8];
__device__ uint2 g_hsplit[2][Bn * 256];            // packed split h (dbl buf)
__device__ uint2 g_xsp[(size_t)BT * 256];          // packed split x
__device__ uint2 g_wihsp[(size_t)H3 * 256];        // packed split W_ih
__device__ uint2 g_woutsp[(size_t)DICTn * Qn * 256]; // packed split W_out

// ---------------- threefry2x32-20 (JAX-exact) --------------------------------
__host__ __device__ inline void threefry2x32(unsigned k0, unsigned k1,
                                             unsigned x0, unsigned x1,
                                             unsigned* o0, unsigned* o1) {
    unsigned ks2 = k0 ^ k1 ^ 0x1BD11BDAu;
    x0 += k0; x1 += k1;
#define TF_R(r) { x0 += x1; x1 = (x1 << (r)) | (x1 >> (32-(r))); x1 ^= x0; }
    TF_R(13) TF_R(15) TF_R(26) TF_R(6)   x0 += k1;  x1 += ks2 + 1u;
    TF_R(17) TF_R(29) TF_R(16) TF_R(24)  x0 += ks2; x1 += k0  + 2u;
    TF_R(13) TF_R(15) TF_R(26) TF_R(6)   x0 += k0;  x1 += k1  + 3u;
    TF_R(17) TF_R(29) TF_R(16) TF_R(24)  x0 += k1;  x1 += ks2 + 4u;
    TF_R(13) TF_R(15) TF_R(26) TF_R(6)   x0 += ks2; x1 += k0  + 5u;
#undef TF_R
    *o0 = x0; *o1 = x1;
}

// fp16x3 split: pack 2 consecutive k. .x = hi pair, .y = lo pair scaled x2048.
__device__ __forceinline__ uint2 splitpk(float2 v) {
    __half hx = __float2half_rn(v.x);
    __half hy = __float2half_rn(v.y);
    float rx = (v.x - __half2float(hx)) * 2048.0f;
    float ry = (v.y - __half2float(hy)) * 2048.0f;
    __half lx = __float2half_rn(rx);
    __half ly = __float2half_rn(ry);
    uint2 r;
    r.x = (unsigned)__half_as_ushort(hx) | ((unsigned)__half_as_ushort(hy) << 16);
    r.y = (unsigned)__half_as_ushort(lx) | ((unsigned)__half_as_ushort(ly) << 16);
    return r;
}

// ---------------- accurate fp32 exp/log --------------------------------------
__device__ __forceinline__ float exp_acc(float x) {
    x = fminf(fmaxf(x, -80.f), 80.f);
    float n = rintf(x * 1.4426950408889634f);
    float r = fmaf(n, -0.6931471824645996f, x);
    r = fmaf(n, 1.9046542121259063e-9f, r);
    float p = 1.984126984e-4f;
    p = fmaf(p, r, 1.388888889e-3f);
    p = fmaf(p, r, 8.333333333e-3f);
    p = fmaf(p, r, 4.166666667e-2f);
    p = fmaf(p, r, 1.666666667e-1f);
    p = fmaf(p, r, 0.5f);
    p = fmaf(p, r, 1.0f);
    p = fmaf(p, r, 1.0f);
    int ni = (int)n;
    float sc = __int_as_float((ni + 127) << 23);
    return p * sc;
}

__device__ __forceinline__ float log_acc(float x) {
    int xi = __float_as_int(x);
    int e = ((xi >> 23) & 0xff) - 127;
    float m = __int_as_float((xi & 0x7fffff) | 0x3f800000);
    if (m > 1.4142135623730951f) { m *= 0.5f; e += 1; }
    float fe = (float)e;
    float s = __fdiv_rn(m - 1.0f, m + 1.0f);
    float s2 = s * s;
    float p = 0.111111111f;
    p = fmaf(p, s2, 0.142857143f);
    p = fmaf(p, s2, 0.2f);
    p = fmaf(p, s2, 0.333333333f);
    p = p * s2;
    float logm = fmaf(2.0f * s, p, 2.0f * s);
    float res = fmaf(fe, 0.6931471824645996f, logm);
    res = fmaf(fe, -1.9046542121259063e-9f, res);
    return res;
}

__device__ __forceinline__ float sigmoid_acc(float x) {
    return __fdiv_rn(1.0f, 1.0f + exp_acc(-x));
}
__device__ __forceinline__ float tanh_acc(float x) {
    float a = fabsf(x);
    float e = exp_acc(-2.0f * a);
    float t = __fdiv_rn(1.0f - e, 1.0f + e);
    return copysignf(t, x);
}

#define MMA16(ACC, A0,A1,A2,A3, B0,B1)                                        \
    asm volatile(                                                             \
        "mma.sync.aligned.m16n8k16.row.col.f32.f16.f16.f32 "                  \
        "{%0,%1,%2,%3}, {%4,%5,%6,%7}, {%8,%9}, {%0,%1,%2,%3};\n"             \
        : "+f"(ACC[0]), "+f"(ACC[1]), "+f"(ACC[2]), "+f"(ACC[3])              \
        : "r"(A0), "r"(A1), "r"(A2), "r"(A3), "r"(B0), "r"(B1))

// per-half named barrier (256 threads each; ids 1 and 2)
#define HBAR(h) asm volatile("bar.sync %0, %1;" :: "r"(1 + (h)), "r"(256) : "memory")

// ---------------- fp16x3 GEMM 128x64 (templated on pre-split operands) -------
template<int PA, int PB>
__global__ __launch_bounds__(256, 2)
void gemm_t(const void* __restrict__ Ap, int lda,
            const void* __restrict__ Bp, int ldb,
            float* __restrict__ C, int ldc,
            int K, const float* __restrict__ bias, int relu,
            const int* __restrict__ row_lens)
{
    __shared__ uint2 As2[128][16];
    __shared__ uint2 Bs2[64][16];

    const float* Af = (const float*)Ap;
    const uint2* Au = (const uint2*)Ap;
    const float* Bf = (const float*)Bp;
    const uint2* Bu = (const uint2*)Bp;
    const int ldau = lda >> 1, ldbu = ldb >> 1;

    const int tid  = threadIdx.x;
    const int warp = tid >> 5, lane = tid & 31;
    const int g    = lane >> 2, tig = lane & 3;
    const int m0   = blockIdx.y * 128, n0 = blockIdx.x * 64;
    const int wm   = (warp >> 1) * 32, wn = (warp & 1) * 32;
    const int swz  = (g & 3) << 2;

    if (row_lens) {
        int b = m0 >> 9;
        int ts = m0 & 511;
        if (ts >= row_lens[b]) return;
    }

    float accH[2][4][4], accC[2][4][4];
#pragma unroll
    for (int mi = 0; mi < 2; mi++)
#pragma unroll
        for (int ni = 0; ni < 4; ni++)
#pragma unroll
            for (int r = 0; r < 4; r++) { accH[mi][ni][r] = 0.f; accC[mi][ni][r] = 0.f; }

    float2 ra2[8], rb2[4];
    uint2  rau[8], rbu[4];
#pragma unroll
    for (int i = 0; i < 8; i++) {
        int idx = tid + i * 256; int m = idx >> 4, kp = idx & 15;
        if (PA) rau[i] = Au[(size_t)(m0 + m) * ldau + kp];
        else    ra2[i] = *(const float2*)(Af + (size_t)(m0 + m) * lda + kp * 2);
    }
#pragma unroll
    for (int i = 0; i < 4; i++) {
        int idx = tid + i * 256; int n = idx >> 4, kp = idx & 15;
        if (PB) rbu[i] = Bu[(size_t)(n0 + n) * ldbu + kp];
        else    rb2[i] = *(const float2*)(Bf + (size_t)(n0 + n) * ldb + kp * 2);
    }

    const int nchunk = K >> 5;
    for (int ch = 0; ch < nchunk; ch++) {
#pragma unroll
        for (int i = 0; i < 8; i++) {
            int idx = tid + i * 256; int m = idx >> 4, kp = idx & 15;
            As2[m][kp ^ ((m & 3) << 2)] = PA ? rau[i] : splitpk(ra2[i]);
        }
#pragma unroll
        for (int i = 0; i < 4; i++) {
            int idx = tid + i * 256; int n = idx >> 4, kp = idx & 15;
            Bs2[n][kp ^ ((n & 3) << 2)] = PB ? rbu[i] : splitpk(rb2[i]);
        }
        __syncthreads();

        if (ch + 1 < nchunk) {
            int k0 = (ch + 1) << 5;
            int kp0 = (ch + 1) << 4;
#pragma unroll
            for (int i = 0; i < 8; i++) {
                int idx = tid + i * 256; int m = idx >> 4, kp = idx & 15;
                if (PA) rau[i] = Au[(size_t)(m0 + m) * ldau + kp0 + kp];
                else    ra2[i] = *(const float2*)(Af + (size_t)(m0 + m) * lda + k0 + kp * 2);
            }
#pragma unroll
            for (int i = 0; i < 4; i++) {
                int idx = tid + i * 256; int n = idx >> 4, kp = idx & 15;
                if (PB) rbu[i] = Bu[(size_t)(n0 + n) * ldbu + kp0 + kp];
                else    rb2[i] = *(const float2*)(Bf + (size_t)(n0 + n) * ldb + k0 + kp * 2);
            }
        }

#pragma unroll
        for (int sub = 0; sub < 2; sub++) {
            int i0 = ((sub << 3) + tig)     ^ swz;
            int i1 = ((sub << 3) + tig + 4) ^ swz;
            uint2 a[2][4];
#pragma unroll
            for (int mi = 0; mi < 2; mi++) {
                int r0 = wm + mi * 16;
                a[mi][0] = As2[r0 + g    ][i0];
                a[mi][1] = As2[r0 + g + 8][i0];
                a[mi][2] = As2[r0 + g    ][i1];
                a[mi][3] = As2[r0 + g + 8][i1];
            }
            uint2 b[4][2];
#pragma unroll
            for (int ni = 0; ni < 4; ni++) {
                int nrow = wn + ni * 8 + g;
                b[ni][0] = Bs2[nrow][i0];
                b[ni][1] = Bs2[nrow][i1];
            }
#pragma unroll
            for (int mi = 0; mi < 2; mi++)
#pragma unroll
                for (int ni = 0; ni < 4; ni++)
                    MMA16(accC[mi][ni], a[mi][0].x,a[mi][1].x,a[mi][2].x,a[mi][3].x,
                          b[ni][0].y, b[ni][1].y);
#pragma unroll
            for (int mi = 0; mi < 2; mi++)
#pragma unroll
                for (int ni = 0; ni < 4; ni++)
                    MMA16(accC[mi][ni], a[mi][0].y,a[mi][1].y,a[mi][2].y,a[mi][3].y,
                          b[ni][0].x, b[ni][1].x);
#pragma unroll
            for (int mi = 0; mi < 2; mi++)
#pragma unroll
                for (int ni = 0; ni < 4; ni++)
                    MMA16(accH[mi][ni], a[mi][0].x,a[mi][1].x,a[mi][2].x,a[mi][3].x,
                          b[ni][0].x, b[ni][1].x);
        }
        __syncthreads();
    }

#pragma unroll
    for (int mi = 0; mi < 2; mi++)
#pragma unroll
        for (int ni = 0; ni < 4; ni++) {
            int r = m0 + wm + mi * 16 + g;
            int c = n0 + wn + ni * 8 + tig * 2;
            float b0 = bias ? bias[c]     : 0.f;
            float b1 = bias ? bias[c + 1] : 0.f;
            float v0 = fmaf(accC[mi][ni][0], INV2048, accH[mi][ni][0]) + b0;
            float v1 = fmaf(accC[mi][ni][1], INV2048, accH[mi][ni][1]) + b1;
            float v2 = fmaf(accC[mi][ni][2], INV2048, accH[mi][ni][2]) + b0;
            float v3 = fmaf(accC[mi][ni][3], INV2048, accH[mi][ni][3]) + b1;
            if (relu) { v0 = fmaxf(v0, 0.f); v1 = fmaxf(v1, 0.f);
                        v2 = fmaxf(v2, 0.f); v3 = fmaxf(v3, 0.f); }
            C[(size_t)r * ldc + c]           = v0;
            C[(size_t)r * ldc + c + 1]       = v1;
            C[(size_t)(r + 8) * ldc + c]     = v2;
            C[(size_t)(r + 8) * ldc + c + 1] = v3;
        }
}

// ---------------- persistent GRU recurrence (v9) -----------------------------
// Split-K 512 threads; per-half named barriers in the K loop; per-group early
// exit at max length.
__device__ __forceinline__ void ld_chunk(const uint2* __restrict__ hs, int m0,
                                         int ch, int t256, uint2* r) {
    int base = ch << 5;
#pragma unroll
    for (int i = 0; i < 4; i++) {
        int idx = t256 + i * 256; int m = idx >> 5, kp = idx & 31;
        r[i] = hs[(size_t)(m0 + m) * 256 + base + kp];
    }
}
__device__ __forceinline__ void st_chunk(uint2* __restrict__ buf, int t256,
                                         const uint2* r) {
#pragma unroll
    for (int i = 0; i < 4; i++) {
        int idx = t256 + i * 256; int m = idx >> 5, kp = idx & 31;
        buf[(m << 5) + (kp & ~15) + ((kp & 15) ^ ((m & 3) << 2))] = r[i];
    }
}

__global__ __launch_bounds__(512, 1)
void gru_persistent(const float* __restrict__ GI,
                    const float* __restrict__ W_hh,
                    const float* __restrict__ b_hh,
                    const int*   __restrict__ lengths,
                    uint2* __restrict__ hsplit,
                    float* __restrict__ hfinal,
                    unsigned* __restrict__ bar)
{
    extern __shared__ uint2 smem2[];
    uint2* Ws2 = smem2;                      // 96*256 uint2 = 196608 B
    uint2* Ab2 = smem2 + WS_UNITS;           // 4 stages x 1024 uint2 = 32768 B
    float* ghp = (float*)(smem2 + WS_UNITS); // [12][256] overlay after K loop

    __shared__ int s_tend;

    const int tid  = threadIdx.x;
    const int warp = tid >> 5, lane = tid & 31;
    const int g    = lane >> 2, tig = lane & 3;
    const int swz  = (g & 3) << 2;
    const int cgp  = blockIdx.x & 15;
    const int bg   = blockIdx.x >> 4;
    const int m0   = bg * 32;
    const int jj0  = cgp * 32;
    const int half = warp >> 3;
    const int w8   = warp & 7;
    const int t256 = tid & 255;
    const int wm   = (w8 & 1) * 16;
    const int jg   = w8 >> 1;
    const bool upper = (half == 1);
    unsigned* mybar = bar + bg;

    for (int i = tid; i < WS_UNITS; i += 512) {
        int n = i >> 8, kp = i & 255;
        int jgn = n / 24, rem = n - jgn * 24;
        int gate = rem >> 3, jo = rem & 7;
        int wrow = gate * Hn + jj0 + jgn * 8 + jo;
        float2 w = *(const float2*)(W_hh + (size_t)wrow * Hn + kp * 2);
        int off = (n << 8) + (kp & ~15) + ((kp & 15) ^ ((n & 3) << 2));
        Ws2[off] = splitpk(w);
    }
    // group max length (warp 0 reduces over the group's 32 rows)
    if (warp == 0) {
        int l = lengths[m0 + lane];
#pragma unroll
        for (int o = 16; o; o >>= 1)
            l = max(l, __shfl_xor_sync(0xffffffffu, l, o));
        if (lane == 0) s_tend = min(l, Tn);
    }
    __syncthreads();
    const int Tend = s_tend;

    const int b0i = m0 + wm + g, b1i = b0i + 8;
    const int jjA = jj0 + jg * 8 + tig * 2, jjB = jjA + 1;
    const int kpidx = jjA >> 1;
    int len0 = 0, len1 = 0;
    float bb[3][2];
    float h_old[4] = {0.f, 0.f, 0.f, 0.f};
    float pg[3][4];
    if (upper) {
        len0 = lengths[b0i]; len1 = lengths[b1i];
#pragma unroll
        for (int gate = 0; gate < 3; gate++) {
            bb[gate][0] = b_hh[gate * Hn + jjA];
            bb[gate][1] = b_hh[gate * Hn + jjB];
        }
#pragma unroll
        for (int gate = 0; gate < 3; gate++) {
            const float* gb = GI + gate * Hn;
            pg[gate][0] = gb[(size_t)b0i * Tn * H3 + jjA];
            pg[gate][1] = gb[(size_t)b0i * Tn * H3 + jjB];
            pg[gate][2] = gb[(size_t)b1i * Tn * H3 + jjA];
            pg[gate][3] = gb[(size_t)b1i * Tn * H3 + jjB];
        }
    }

    uint2* stage0 = Ab2 + half * 2048;
    uint2* stage1 = stage0 + 1024;
    const int ch0 = half * 4;

    for (int t = 0; t < Tend; t++) {
        const uint2* hs_in = hsplit + (t & 1) * (Bn * 256);
        uint2*      hs_out = hsplit + ((t + 1) & 1) * (Bn * 256);

        float accP[3][4], accQ[3][4], accR[3][4];
#pragma unroll
        for (int nt = 0; nt < 3; nt++)
#pragma unroll
            for (int r = 0; r < 4; r++) {
                accP[nt][r] = 0.f; accQ[nt][r] = 0.f; accR[nt][r] = 0.f;
            }

        uint2 rA[4];
        ld_chunk(hs_in, m0, ch0, t256, rA);
        st_chunk(stage0, t256, rA);
        ld_chunk(hs_in, m0, ch0 + 1, t256, rA);
        HBAR(half);

#pragma unroll
        for (int it = 0; it < 4; it++) {
            const uint2* Ah = (it & 1) ? stage1 : stage0;
            const int chbase = (ch0 + it) << 5;
#pragma unroll
            for (int sub = 0; sub < 4; sub++) {
                int i0 = ((sub << 3) + tig)     ^ swz;
                int i1 = ((sub << 3) + tig + 4) ^ swz;
                uint2 a0 = Ah[((wm + g)     << 5) + i0];
                uint2 a1 = Ah[((wm + g + 8) << 5) + i0];
                uint2 a2 = Ah[((wm + g)     << 5) + i1];
                uint2 a3 = Ah[((wm + g + 8) << 5) + i1];
                uint2 b0v[3], b1v[3];
#pragma unroll
                for (int nt = 0; nt < 3; nt++) {
                    int nrow = jg * 24 + nt * 8 + g;
                    int base = (nrow << 8) + chbase;
                    b0v[nt] = Ws2[base + i0];
                    b1v[nt] = Ws2[base + i1];
                }
#pragma unroll
                for (int nt = 0; nt < 3; nt++)
                    MMA16(accQ[nt], a0.x, a1.x, a2.x, a3.x, b0v[nt].y, b1v[nt].y);
#pragma unroll
                for (int nt = 0; nt < 3; nt++)
                    MMA16(accR[nt], a0.y, a1.y, a2.y, a3.y, b0v[nt].x, b1v[nt].x);
#pragma unroll
                for (int nt = 0; nt < 3; nt++)
                    MMA16(accP[nt], a0.x, a1.x, a2.x, a3.x, b0v[nt].x, b1v[nt].x);
            }
            if (it < 3) {
                st_chunk((it & 1) ? stage0 : stage1, t256, rA);
                if (it < 2) ld_chunk(hs_in, m0, ch0 + it + 2, t256, rA);
            }
            HBAR(half);
        }

        float part[12];
#pragma unroll
        for (int nt = 0; nt < 3; nt++)
#pragma unroll
            for (int k = 0; k < 4; k++)
                part[nt * 4 + k] = fmaf(accQ[nt][k] + accR[nt][k], INV2048,
                                        accP[nt][k]);
        if (!upper) {
#pragma unroll
            for (int i = 0; i < 12; i++)
                ghp[i * 256 + t256] = part[i];
        }
        __syncthreads();

        if (upper) {
            float gh[3][4];
#pragma unroll
            for (int nt = 0; nt < 3; nt++)
#pragma unroll
                for (int k = 0; k < 4; k++)
                    gh[nt][k] = part[nt * 4 + k] + ghp[(nt * 4 + k) * 256 + t256]
                              + bb[nt][k & 1];
#pragma unroll
            for (int k = 0; k < 4; k++) {
                float r = sigmoid_acc(pg[0][k] + gh[0][k]);
                float z = sigmoid_acc(pg[1][k] + gh[1][k]);
                float n = tanh_acc(fmaf(r, gh[2][k], pg[2][k]));
                int blen = (k < 2) ? len0 : len1;
                float hv = (1.f - z) * n + z * h_old[k];
                h_old[k] = (t < blen) ? hv : h_old[k];
            }
            if (t + 1 < Tend) {
                hs_out[(size_t)b0i * 256 + kpidx] = splitpk(make_float2(h_old[0], h_old[1]));
                hs_out[(size_t)b1i * 256 + kpidx] = splitpk(make_float2(h_old[2], h_old[3]));
            } else {
                hfinal[(size_t)b0i * Hn + jjA] = h_old[0];
                hfinal[(size_t)b0i * Hn + jjB] = h_old[1];
                hfinal[(size_t)b1i * Hn + jjA] = h_old[2];
                hfinal[(size_t)b1i * Hn + jjB] = h_old[3];
            }
        }

        if (t + 1 >= Tend) break;   // no barrier needed after the last step

        __syncthreads();
        if (tid == 0) {
            asm volatile("red.release.gpu.global.add.u32 [%0], %1;"
                         :: "l"(mybar), "r"(1u) : "memory");
        }
        if (upper) {
            size_t off0 = ((size_t)b0i * Tn + (t + 1)) * H3;
            size_t off1 = ((size_t)b1i * Tn + (t + 1)) * H3;
#pragma unroll
            for (int gate = 0; gate < 3; gate++) {
                pg[gate][0] = GI[off0 + gate * Hn + jjA];
                pg[gate][1] = GI[off0 + gate * Hn + jjB];
                pg[gate][2] = GI[off1 + gate * Hn + jjA];
                pg[gate][3] = GI[off1 + gate * Hn + jjB];
            }
        }
        if (tid == 0) {
            unsigned target = 16u * (unsigned)(t + 1);
            unsigned v;
            do {
                asm volatile("ld.acquire.gpu.global.b32 %0, [%1];"
                             : "=r"(v) : "l"(mybar) : "memory");
                if (v < target) __nanosleep(16);
            } while (v < target);
        }
        __syncthreads();
    }
}

// ---------------- misc -------------------------------------------------------
__global__ void init_kernel(uint2* hs0, unsigned* bar) {
    int i = blockIdx.x * blockDim.x + threadIdx.x;
    if (i < Bn * 256) hs0[i] = make_uint2(0u, 0u);
    if (i < 8) bar[i] = 0u;
}

#define XSP_N   ((size_t)BT * 256)
#define WSP_N   ((size_t)H3 * 256)
#define WOSP_N  ((size_t)DICTn * Qn * 256)
__global__ void presplit_kernel(const float* __restrict__ x,
                                const float* __restrict__ wih,
                                const float* __restrict__ wout,
                                uint2* __restrict__ xsp,
                                uint2* __restrict__ wsp,
                                uint2* __restrict__ wosp)
{
    size_t i = (size_t)blockIdx.x * 256 + threadIdx.x;
    if (i < XSP_N) {
        xsp[i] = splitpk(((const float2*)x)[i]);
    } else if (i < XSP_N + WSP_N) {
        size_t j = i - XSP_N;
        wsp[j] = splitpk(((const float2*)wih)[j]);
    } else {
        size_t j = i - XSP_N - WSP_N;
        if (j < WOSP_N) wosp[j] = splitpk(((const float2*)wout)[j]);
    }
}

__global__ void value_kernel(const float* __restrict__ h2,
                             const float* __restrict__ Wc3,
                             const float* __restrict__ bc3,
                             float* __restrict__ out)
{
    int gw = (blockIdx.x * blockDim.x + threadIdx.x) >> 5;
    int lane = threadIdx.x & 31;
    if (gw >= Bn) return;
    float s = 0.f;
    for (int k = lane; k < Hn; k += 32) s = fmaf(h2[gw * Hn + k], Wc3[k], s);
#pragma unroll
    for (int o = 16; o; o >>= 1) s += __shfl_xor_sync(0xffffffffu, s, o);
    if (lane == 0) out[gw] = s + bc3[0];
}

// fused log-softmax + inline threefry gumbel + categorical sample + one-hot
__global__ __launch_bounds__(256)
void sample_kernel(const float* __restrict__ logits,
                   unsigned k0, unsigned k1,
                   float* __restrict__ out_query,
                   float* __restrict__ out_lp)
{
    __shared__ float red[256];
    __shared__ int   redi[256];
    int row = blockIdx.x;
    int tid = threadIdx.x;
    const float* lg = logits + (size_t)row * DICTn;

    float l[4];
#pragma unroll
    for (int i = 0; i < 4; i++) l[i] = lg[tid + i * 256];

    float mx = fmaxf(fmaxf(l[0], l[1]), fmaxf(l[2], l[3]));
    red[tid] = mx; __syncthreads();
    for (int s = 128; s > 0; s >>= 1) {
        if (tid < s) red[tid] = fmaxf(red[tid], red[tid + s]);
        __syncthreads();
    }
    mx = red[0]; __syncthreads();

    float se = 0.f;
#pragma unroll
    for (int i = 0; i < 4; i++) se += exp_acc(l[i] - mx);
    red[tid] = se; __syncthreads();
    for (int s = 128; s > 0; s >>= 1) {
        if (tid < s) red[tid] += red[tid + s];
        __syncthreads();
    }
    float logZ = mx + log_acc(red[0]); __syncthreads();

    float bv = -1e30f; int bi = 0x7fffffff;
#pragma unroll
    for (int i = 0; i < 4; i++) {
        int idx = tid + i * 256;
        float lp = l[i] - logZ;
        out_lp[(size_t)row * DICTn + idx] = lp;
        unsigned gidx = (unsigned)row * DICTn + idx;
        unsigned o0, o1;
        threefry2x32(k0, k1, 0u, gidx, &o0, &o1);
        unsigned bits = o0 ^ o1;
        float f = __uint_as_float((bits >> 9) | 0x3f800000u) - 1.0f;
        float u = fmaxf(f, 1.17549435e-38f);
        float gum = -log_acc(-log_acc(u));
        float v = lp + gum;
        if (v > bv || (v == bv && idx < bi)) { bv = v; bi = idx; }
    }
    red[tid] = bv; redi[tid] = bi; __syncthreads();
    for (int s = 128; s > 0; s >>= 1) {
        if (tid < s) {
            if (red[tid + s] > red[tid] ||
                (red[tid + s] == red[tid] && redi[tid + s] < redi[tid])) {
                red[tid] = red[tid + s]; redi[tid] = redi[tid + s];
            }
        }
        __syncthreads();
    }
    int win = redi[0];
#pragma unroll
    for (int i = 0; i < 4; i++) {
        int idx = tid + i * 256;
        out_query[(size_t)row * DICTn + idx] = (idx == win) ? 1.f : 0.f;
    }
}

// ---------------- host -------------------------------------------------------
extern "C" void kernel_launch(void* const* d_in, const int* in_sizes, int n_in,
                              void* d_out, int out_size)
{
    const float* x      = (const float*)d_in[0];
    const int*   lens   = (const int*)  d_in[1];
    const float* W_ih   = (const float*)d_in[2];
    const float* W_hh   = (const float*)d_in[3];
    const float* b_ih   = (const float*)d_in[4];
    const float* b_hh   = (const float*)d_in[5];
    const float* W_out  = (const float*)d_in[6];
    const float* b_out  = (const float*)d_in[7];
    const float* Wc1    = (const float*)d_in[8];
    const float* bc1    = (const float*)d_in[9];
    const float* Wc2    = (const float*)d_in[10];
    const float* bc2    = (const float*)d_in[11];
    const float* Wc3    = (const float*)d_in[12];
    const float* bc3    = (const float*)d_in[13];

    float* out_value = (float*)d_out;
    float* out_query = out_value + Bn;
    float* out_lp    = out_query + (size_t)NSAMP;

    float *pGI, *ph, *pc1, *pc2, *plog;
    unsigned* pbar;
    uint2 *phs, *pxsp, *pwsp, *pwosp;
    cudaGetSymbolAddress((void**)&pGI,  g_GI);
    cudaGetSymbolAddress((void**)&ph,   g_h);
    cudaGetSymbolAddress((void**)&pc1,  g_c1);
    cudaGetSymbolAddress((void**)&pc2,  g_c2);
    cudaGetSymbolAddress((void**)&plog, g_logits);
    cudaGetSymbolAddress((void**)&pbar, g_barrier);
    cudaGetSymbolAddress((void**)&phs,  g_hsplit);
    cudaGetSymbolAddress((void**)&pxsp, g_xsp);
    cudaGetSymbolAddress((void**)&pwsp, g_wihsp);
    cudaGetSymbolAddress((void**)&pwosp, g_woutsp);

    const int rec_smem = WS_UNITS * 8 + 4 * 1024 * 8;   // 229376 B
    cudaFuncSetAttribute(gru_persistent,
        cudaFuncAttributeMaxDynamicSharedMemorySize, rec_smem);

    // 1) zero split-h buffer 0 + barriers
    init_kernel<<<(Bn * 256 + 255) / 256, 256>>>(phs, pbar);

    // 2) pre-split x, W_ih, W_out (packed fp16 hi/lo)
    presplit_kernel<<<(unsigned)((XSP_N + WSP_N + WOSP_N + 255) / 256), 256>>>(
        x, W_ih, W_out, pxsp, pwsp, pwosp);

    // 3) GI = x @ W_ih^T + b_ih
    gemm_t<1,1><<<dim3(H3 / 64, BT / 128), 256>>>(pxsp, Dn, pwsp, Dn,
                                                  pGI, H3, Dn, b_ih, 0, lens);

    // 4) persistent recurrence
    gru_persistent<<<NCTA_REC, 512, rec_smem>>>(pGI, W_hh, b_hh, lens,
                                                phs, ph, pbar);
    float* hfin = ph;

    // 5) critic (fp32 h operand; hfinal is fp32)
    gemm_t<0,0><<<dim3(Hn / 64, Bn / 128), 256>>>(hfin, Hn, Wc1, Hn,
                                                  pc1, Hn, Hn, bc1, 1, nullptr);
    gemm_t<0,0><<<dim3(Hn / 64, Bn / 128), 256>>>(pc1, Hn, Wc2, Hn,
                                                  pc2, Hn, Hn, bc2, 1, nullptr);
    value_kernel<<<(Bn * 32 + 255) / 256, 256>>>(pc2, Wc3, bc3, out_value);

    // 6) actor logits (fp32 h x presplit W_out)
    gemm_t<0,1><<<dim3(DICTn * Qn / 64, Bn / 128), 256>>>(
        hfin, Hn, pwosp, Hn, plog, DICTn * Qn, Hn, b_out, 0, nullptr);

    // 7) fused log-softmax + gumbel + sample (skey = fold_in(key(0),1234))
    unsigned s0, s1;
    threefry2x32(0u, 0u, 0u, 1234u, &s0, &s1);
    sample_kernel<<<Bn * Qn, 256>>>(plog, s0, s1, out_query, out_lp);
}

// round 17
// speedup vs baseline: 1.1677x; 1.1677x over previous
#include <cuda_runtime.h>
#include <cuda_fp16.h>
#include <math.h>
#include <stdint.h>

#define Bn    256
#define Tn    512
#define Dn    512
#define Hn    512
#define H3    1536
#define DICTn 1024
#define Qn    32
#define BT    (Bn*Tn)
#define NSAMP (Bn*Qn*DICTn)   // 8388608

#define NCTA_REC 128
#define WS_UNITS (96*256)     // W slice uint2 units (96 gh rows x 256 k-pairs)
#define INV2048  4.8828125e-4f

// ---------------- static device scratch -------------------------------------
__device__ float g_GI[(size_t)BT * H3];
__device__ float g_h[2][Bn * Hn];
__device__ float g_c1[Bn * Hn];
__device__ float g_c2[Bn * Hn];
__device__ float g_logits[(size_t)Bn * Qn * DICTn];
__device__ unsigned g_barrier[8];
__device__ uint2 g_hsplit[2][Bn * 256];            // packed split h (dbl buf)
__device__ uint2 g_xsp[(size_t)BT * 256];          // packed split x
__device__ uint2 g_wihsp[(size_t)H3 * 256];        // packed split W_ih
__device__ uint2 g_woutsp[(size_t)DICTn * Qn * 256]; // packed split W_out

// ---------------- threefry2x32-20 (JAX-exact) --------------------------------
__host__ __device__ inline void threefry2x32(unsigned k0, unsigned k1,
                                             unsigned x0, unsigned x1,
                                             unsigned* o0, unsigned* o1) {
    unsigned ks2 = k0 ^ k1 ^ 0x1BD11BDAu;
    x0 += k0; x1 += k1;
#define TF_R(r) { x0 += x1; x1 = (x1 << (r)) | (x1 >> (32-(r))); x1 ^= x0; }
    TF_R(13) TF_R(15) TF_R(26) TF_R(6)   x0 += k1;  x1 += ks2 + 1u;
    TF_R(17) TF_R(29) TF_R(16) TF_R(24)  x0 += ks2; x1 += k0  + 2u;
    TF_R(13) TF_R(15) TF_R(26) TF_R(6)   x0 += k0;  x1 += k1  + 3u;
    TF_R(17) TF_R(29) TF_R(16) TF_R(24)  x0 += k1;  x1 += ks2 + 4u;
    TF_R(13) TF_R(15) TF_R(26) TF_R(6)   x0 += ks2; x1 += k0  + 5u;
#undef TF_R
    *o0 = x0; *o1 = x1;
}

// fp16x3 split: pack 2 consecutive k. .x = hi pair, .y = lo pair scaled x2048.
__device__ __forceinline__ uint2 splitpk(float2 v) {
    __half hx = __float2half_rn(v.x);
    __half hy = __float2half_rn(v.y);
    float rx = (v.x - __half2float(hx)) * 2048.0f;
    float ry = (v.y - __half2float(hy)) * 2048.0f;
    __half lx = __float2half_rn(rx);
    __half ly = __float2half_rn(ry);
    uint2 r;
    r.x = (unsigned)__half_as_ushort(hx) | ((unsigned)__half_as_ushort(hy) << 16);
    r.y = (unsigned)__half_as_ushort(lx) | ((unsigned)__half_as_ushort(ly) << 16);
    return r;
}

// ---------------- accurate fp32 exp/log --------------------------------------
__device__ __forceinline__ float exp_acc(float x) {
    x = fminf(fmaxf(x, -80.f), 80.f);
    float n = rintf(x * 1.4426950408889634f);
    float r = fmaf(n, -0.6931471824645996f, x);
    r = fmaf(n, 1.9046542121259063e-9f, r);
    float p = 1.984126984e-4f;
    p = fmaf(p, r, 1.388888889e-3f);
    p = fmaf(p, r, 8.333333333e-3f);
    p = fmaf(p, r, 4.166666667e-2f);
    p = fmaf(p, r, 1.666666667e-1f);
    p = fmaf(p, r, 0.5f);
    p = fmaf(p, r, 1.0f);
    p = fmaf(p, r, 1.0f);
    int ni = (int)n;
    float sc = __int_as_float((ni + 127) << 23);
    return p * sc;
}

__device__ __forceinline__ float log_acc(float x) {
    int xi = __float_as_int(x);
    int e = ((xi >> 23) & 0xff) - 127;
    float m = __int_as_float((xi & 0x7fffff) | 0x3f800000);
    if (m > 1.4142135623730951f) { m *= 0.5f; e += 1; }
    float fe = (float)e;
    float s = __fdiv_rn(m - 1.0f, m + 1.0f);
    float s2 = s * s;
    float p = 0.111111111f;
    p = fmaf(p, s2, 0.142857143f);
    p = fmaf(p, s2, 0.2f);
    p = fmaf(p, s2, 0.333333333f);
    p = p * s2;
    float logm = fmaf(2.0f * s, p, 2.0f * s);
    float res = fmaf(fe, 0.6931471824645996f, logm);
    res = fmaf(fe, -1.9046542121259063e-9f, res);
    return res;
}

__device__ __forceinline__ float sigmoid_acc(float x) {
    return __fdiv_rn(1.0f, 1.0f + exp_acc(-x));
}
__device__ __forceinline__ float tanh_acc(float x) {
    float a = fabsf(x);
    float e = exp_acc(-2.0f * a);
    float t = __fdiv_rn(1.0f - e, 1.0f + e);
    return copysignf(t, x);
}

#define MMA16(ACC, A0,A1,A2,A3, B0,B1)                                        \
    asm volatile(                                                             \
        "mma.sync.aligned.m16n8k16.row.col.f32.f16.f16.f32 "                  \
        "{%0,%1,%2,%3}, {%4,%5,%6,%7}, {%8,%9}, {%0,%1,%2,%3};\n"             \
        : "+f"(ACC[0]), "+f"(ACC[1]), "+f"(ACC[2]), "+f"(ACC[3])              \
        : "r"(A0), "r"(A1), "r"(A2), "r"(A3), "r"(B0), "r"(B1))

// per-half named barrier (256 threads each; ids 1 and 2)
#define HBAR(h) asm volatile("bar.sync %0, %1;" :: "r"(1 + (h)), "r"(256) : "memory")

// ---------------- fp16x3 GEMM 128x64 (templated on pre-split operands) -------
template<int PA, int PB>
__global__ __launch_bounds__(256)
void gemm_t(const void* __restrict__ Ap, int lda,
            const void* __restrict__ Bp, int ldb,
            float* __restrict__ C, int ldc,
            int K, const float* __restrict__ bias, int relu,
            const int* __restrict__ row_lens)
{
    __shared__ uint2 As2[128][16];
    __shared__ uint2 Bs2[64][16];

    const float* Af = (const float*)Ap;
    const uint2* Au = (const uint2*)Ap;
    const float* Bf = (const float*)Bp;
    const uint2* Bu = (const uint2*)Bp;
    const int ldau = lda >> 1, ldbu = ldb >> 1;

    const int tid  = threadIdx.x;
    const int warp = tid >> 5, lane = tid & 31;
    const int g    = lane >> 2, tig = lane & 3;
    const int m0   = blockIdx.y * 128, n0 = blockIdx.x * 64;
    const int wm   = (warp >> 1) * 32, wn = (warp & 1) * 32;
    const int swz  = (g & 3) << 2;

    if (row_lens) {
        int b = m0 >> 9;
        int ts = m0 & 511;
        if (ts >= row_lens[b]) return;
    }

    float accH[2][4][4], accC[2][4][4];
#pragma unroll
    for (int mi = 0; mi < 2; mi++)
#pragma unroll
        for (int ni = 0; ni < 4; ni++)
#pragma unroll
            for (int r = 0; r < 4; r++) { accH[mi][ni][r] = 0.f; accC[mi][ni][r] = 0.f; }

    float2 ra2[8], rb2[4];
    uint2  rau[8], rbu[4];
#pragma unroll
    for (int i = 0; i < 8; i++) {
        int idx = tid + i * 256; int m = idx >> 4, kp = idx & 15;
        if (PA) rau[i] = Au[(size_t)(m0 + m) * ldau + kp];
        else    ra2[i] = *(const float2*)(Af + (size_t)(m0 + m) * lda + kp * 2);
    }
#pragma unroll
    for (int i = 0; i < 4; i++) {
        int idx = tid + i * 256; int n = idx >> 4, kp = idx & 15;
        if (PB) rbu[i] = Bu[(size_t)(n0 + n) * ldbu + kp];
        else    rb2[i] = *(const float2*)(Bf + (size_t)(n0 + n) * ldb + kp * 2);
    }

    const int nchunk = K >> 5;
    for (int ch = 0; ch < nchunk; ch++) {
#pragma unroll
        for (int i = 0; i < 8; i++) {
            int idx = tid + i * 256; int m = idx >> 4, kp = idx & 15;
            As2[m][kp ^ ((m & 3) << 2)] = PA ? rau[i] : splitpk(ra2[i]);
        }
#pragma unroll
        for (int i = 0; i < 4; i++) {
            int idx = tid + i * 256; int n = idx >> 4, kp = idx & 15;
            Bs2[n][kp ^ ((n & 3) << 2)] = PB ? rbu[i] : splitpk(rb2[i]);
        }
        __syncthreads();

        if (ch + 1 < nchunk) {
            int k0 = (ch + 1) << 5;
            int kp0 = (ch + 1) << 4;
#pragma unroll
            for (int i = 0; i < 8; i++) {
                int idx = tid + i * 256; int m = idx >> 4, kp = idx & 15;
                if (PA) rau[i] = Au[(size_t)(m0 + m) * ldau + kp0 + kp];
                else    ra2[i] = *(const float2*)(Af + (size_t)(m0 + m) * lda + k0 + kp * 2);
            }
#pragma unroll
            for (int i = 0; i < 4; i++) {
                int idx = tid + i * 256; int n = idx >> 4, kp = idx & 15;
                if (PB) rbu[i] = Bu[(size_t)(n0 + n) * ldbu + kp0 + kp];
                else    rb2[i] = *(const float2*)(Bf + (size_t)(n0 + n) * ldb + k0 + kp * 2);
            }
        }

#pragma unroll
        for (int sub = 0; sub < 2; sub++) {
            int i0 = ((sub << 3) + tig)     ^ swz;
            int i1 = ((sub << 3) + tig + 4) ^ swz;
            uint2 a[2][4];
#pragma unroll
            for (int mi = 0; mi < 2; mi++) {
                int r0 = wm + mi * 16;
                a[mi][0] = As2[r0 + g    ][i0];
                a[mi][1] = As2[r0 + g + 8][i0];
                a[mi][2] = As2[r0 + g    ][i1];
                a[mi][3] = As2[r0 + g + 8][i1];
            }
            uint2 b[4][2];
#pragma unroll
            for (int ni = 0; ni < 4; ni++) {
                int nrow = wn + ni * 8 + g;
                b[ni][0] = Bs2[nrow][i0];
                b[ni][1] = Bs2[nrow][i1];
            }
#pragma unroll
            for (int mi = 0; mi < 2; mi++)
#pragma unroll
                for (int ni = 0; ni < 4; ni++)
                    MMA16(accC[mi][ni], a[mi][0].x,a[mi][1].x,a[mi][2].x,a[mi][3].x,
                          b[ni][0].y, b[ni][1].y);
#pragma unroll
            for (int mi = 0; mi < 2; mi++)
#pragma unroll
                for (int ni = 0; ni < 4; ni++)
                    MMA16(accC[mi][ni], a[mi][0].y,a[mi][1].y,a[mi][2].y,a[mi][3].y,
                          b[ni][0].x, b[ni][1].x);
#pragma unroll
            for (int mi = 0; mi < 2; mi++)
#pragma unroll
                for (int ni = 0; ni < 4; ni++)
                    MMA16(accH[mi][ni], a[mi][0].x,a[mi][1].x,a[mi][2].x,a[mi][3].x,
                          b[ni][0].x, b[ni][1].x);
        }
        __syncthreads();
    }

#pragma unroll
    for (int mi = 0; mi < 2; mi++)
#pragma unroll
        for (int ni = 0; ni < 4; ni++) {
            int r = m0 + wm + mi * 16 + g;
            int c = n0 + wn + ni * 8 + tig * 2;
            float b0 = bias ? bias[c]     : 0.f;
            float b1 = bias ? bias[c + 1] : 0.f;
            float v0 = fmaf(accC[mi][ni][0], INV2048, accH[mi][ni][0]) + b0;
            float v1 = fmaf(accC[mi][ni][1], INV2048, accH[mi][ni][1]) + b1;
            float v2 = fmaf(accC[mi][ni][2], INV2048, accH[mi][ni][2]) + b0;
            float v3 = fmaf(accC[mi][ni][3], INV2048, accH[mi][ni][3]) + b1;
            if (relu) { v0 = fmaxf(v0, 0.f); v1 = fmaxf(v1, 0.f);
                        v2 = fmaxf(v2, 0.f); v3 = fmaxf(v3, 0.f); }
            C[(size_t)r * ldc + c]           = v0;
            C[(size_t)r * ldc + c + 1]       = v1;
            C[(size_t)(r + 8) * ldc + c]     = v2;
            C[(size_t)(r + 8) * ldc + c + 1] = v3;
        }
}

// ---------------- persistent GRU recurrence (v9) -----------------------------
// Split-K 512 threads; per-half named barriers in the K loop; per-group early
// exit at max length.
__device__ __forceinline__ void ld_chunk(const uint2* __restrict__ hs, int m0,
                                         int ch, int t256, uint2* r) {
    int base = ch << 5;
#pragma unroll
    for (int i = 0; i < 4; i++) {
        int idx = t256 + i * 256; int m = idx >> 5, kp = idx & 31;
        r[i] = hs[(size_t)(m0 + m) * 256 + base + kp];
    }
}
__device__ __forceinline__ void st_chunk(uint2* __restrict__ buf, int t256,
                                         const uint2* r) {
#pragma unroll
    for (int i = 0; i < 4; i++) {
        int idx = t256 + i * 256; int m = idx >> 5, kp = idx & 31;
        buf[(m << 5) + (kp & ~15) + ((kp & 15) ^ ((m & 3) << 2))] = r[i];
    }
}

__global__ __launch_bounds__(512, 1)
void gru_persistent(const float* __restrict__ GI,
                    const float* __restrict__ W_hh,
                    const float* __restrict__ b_hh,
                    const int*   __restrict__ lengths,
                    uint2* __restrict__ hsplit,
                    float* __restrict__ hfinal,
                    unsigned* __restrict__ bar)
{
    extern __shared__ uint2 smem2[];
    uint2* Ws2 = smem2;                      // 96*256 uint2 = 196608 B
    uint2* Ab2 = smem2 + WS_UNITS;           // 4 stages x 1024 uint2 = 32768 B
    float* ghp = (float*)(smem2 + WS_UNITS); // [12][256] overlay after K loop

    __shared__ int s_tend;

    const int tid  = threadIdx.x;
    const int warp = tid >> 5, lane = tid & 31;
    const int g    = lane >> 2, tig = lane & 3;
    const int swz  = (g & 3) << 2;
    const int cgp  = blockIdx.x & 15;
    const int bg   = blockIdx.x >> 4;
    const int m0   = bg * 32;
    const int jj0  = cgp * 32;
    const int half = warp >> 3;
    const int w8   = warp & 7;
    const int t256 = tid & 255;
    const int wm   = (w8 & 1) * 16;
    const int jg   = w8 >> 1;
    const bool upper = (half == 1);
    unsigned* mybar = bar + bg;

    for (int i = tid; i < WS_UNITS; i += 512) {
        int n = i >> 8, kp = i & 255;
        int jgn = n / 24, rem = n - jgn * 24;
        int gate = rem >> 3, jo = rem & 7;
        int wrow = gate * Hn + jj0 + jgn * 8 + jo;
        float2 w = *(const float2*)(W_hh + (size_t)wrow * Hn + kp * 2);
        int off = (n << 8) + (kp & ~15) + ((kp & 15) ^ ((n & 3) << 2));
        Ws2[off] = splitpk(w);
    }
    // group max length (warp 0 reduces over the group's 32 rows)
    if (warp == 0) {
        int l = lengths[m0 + lane];
#pragma unroll
        for (int o = 16; o; o >>= 1)
            l = max(l, __shfl_xor_sync(0xffffffffu, l, o));
        if (lane == 0) s_tend = min(l, Tn);
    }
    __syncthreads();
    const int Tend = s_tend;

    const int b0i = m0 + wm + g, b1i = b0i + 8;
    const int jjA = jj0 + jg * 8 + tig * 2, jjB = jjA + 1;
    const int kpidx = jjA >> 1;
    int len0 = 0, len1 = 0;
    float bb[3][2];
    float h_old[4] = {0.f, 0.f, 0.f, 0.f};
    float pg[3][4];
    if (upper) {
        len0 = lengths[b0i]; len1 = lengths[b1i];
#pragma unroll
        for (int gate = 0; gate < 3; gate++) {
            bb[gate][0] = b_hh[gate * Hn + jjA];
            bb[gate][1] = b_hh[gate * Hn + jjB];
        }
#pragma unroll
        for (int gate = 0; gate < 3; gate++) {
            const float* gb = GI + gate * Hn;
            pg[gate][0] = gb[(size_t)b0i * Tn * H3 + jjA];
            pg[gate][1] = gb[(size_t)b0i * Tn * H3 + jjB];
            pg[gate][2] = gb[(size_t)b1i * Tn * H3 + jjA];
            pg[gate][3] = gb[(size_t)b1i * Tn * H3 + jjB];
        }
    }

    uint2* stage0 = Ab2 + half * 2048;
    uint2* stage1 = stage0 + 1024;
    const int ch0 = half * 4;

    for (int t = 0; t < Tend; t++) {
        const uint2* hs_in = hsplit + (t & 1) * (Bn * 256);
        uint2*      hs_out = hsplit + ((t + 1) & 1) * (Bn * 256);

        float accP[3][4], accQ[3][4], accR[3][4];
#pragma unroll
        for (int nt = 0; nt < 3; nt++)
#pragma unroll
            for (int r = 0; r < 4; r++) {
                accP[nt][r] = 0.f; accQ[nt][r] = 0.f; accR[nt][r] = 0.f;
            }

        uint2 rA[4];
        ld_chunk(hs_in, m0, ch0, t256, rA);
        st_chunk(stage0, t256, rA);
        ld_chunk(hs_in, m0, ch0 + 1, t256, rA);
        HBAR(half);

#pragma unroll
        for (int it = 0; it < 4; it++) {
            const uint2* Ah = (it & 1) ? stage1 : stage0;
            const int chbase = (ch0 + it) << 5;
#pragma unroll
            for (int sub = 0; sub < 4; sub++) {
                int i0 = ((sub << 3) + tig)     ^ swz;
                int i1 = ((sub << 3) + tig + 4) ^ swz;
                uint2 a0 = Ah[((wm + g)     << 5) + i0];
                uint2 a1 = Ah[((wm + g + 8) << 5) + i0];
                uint2 a2 = Ah[((wm + g)     << 5) + i1];
                uint2 a3 = Ah[((wm + g + 8) << 5) + i1];
                uint2 b0v[3], b1v[3];
#pragma unroll
                for (int nt = 0; nt < 3; nt++) {
                    int nrow = jg * 24 + nt * 8 + g;
                    int base = (nrow << 8) + chbase;
                    b0v[nt] = Ws2[base + i0];
                    b1v[nt] = Ws2[base + i1];
                }
#pragma unroll
                for (int nt = 0; nt < 3; nt++)
                    MMA16(accQ[nt], a0.x, a1.x, a2.x, a3.x, b0v[nt].y, b1v[nt].y);
#pragma unroll
                for (int nt = 0; nt < 3; nt++)
                    MMA16(accR[nt], a0.y, a1.y, a2.y, a3.y, b0v[nt].x, b1v[nt].x);
#pragma unroll
                for (int nt = 0; nt < 3; nt++)
                    MMA16(accP[nt], a0.x, a1.x, a2.x, a3.x, b0v[nt].x, b1v[nt].x);
            }
            if (it < 3) {
                st_chunk((it & 1) ? stage0 : stage1, t256, rA);
                if (it < 2) ld_chunk(hs_in, m0, ch0 + it + 2, t256, rA);
            }
            HBAR(half);
        }

        float part[12];
#pragma unroll
        for (int nt = 0; nt < 3; nt++)
#pragma unroll
            for (int k = 0; k < 4; k++)
                part[nt * 4 + k] = fmaf(accQ[nt][k] + accR[nt][k], INV2048,
                                        accP[nt][k]);
        if (!upper) {
#pragma unroll
            for (int i = 0; i < 12; i++)
                ghp[i * 256 + t256] = part[i];
        }
        __syncthreads();

        if (upper) {
            float gh[3][4];
#pragma unroll
            for (int nt = 0; nt < 3; nt++)
#pragma unroll
                for (int k = 0; k < 4; k++)
                    gh[nt][k] = part[nt * 4 + k] + ghp[(nt * 4 + k) * 256 + t256]
                              + bb[nt][k & 1];
#pragma unroll
            for (int k = 0; k < 4; k++) {
                float r = sigmoid_acc(pg[0][k] + gh[0][k]);
                float z = sigmoid_acc(pg[1][k] + gh[1][k]);
                float n = tanh_acc(fmaf(r, gh[2][k], pg[2][k]));
                int blen = (k < 2) ? len0 : len1;
                float hv = (1.f - z) * n + z * h_old[k];
                h_old[k] = (t < blen) ? hv : h_old[k];
            }
            if (t + 1 < Tend) {
                hs_out[(size_t)b0i * 256 + kpidx] = splitpk(make_float2(h_old[0], h_old[1]));
                hs_out[(size_t)b1i * 256 + kpidx] = splitpk(make_float2(h_old[2], h_old[3]));
            } else {
                hfinal[(size_t)b0i * Hn + jjA] = h_old[0];
                hfinal[(size_t)b0i * Hn + jjB] = h_old[1];
                hfinal[(size_t)b1i * Hn + jjA] = h_old[2];
                hfinal[(size_t)b1i * Hn + jjB] = h_old[3];
            }
        }

        if (t + 1 >= Tend) break;   // no barrier needed after the last step

        __syncthreads();
        if (tid == 0) {
            asm volatile("red.release.gpu.global.add.u32 [%0], %1;"
                         :: "l"(mybar), "r"(1u) : "memory");
        }
        if (upper) {
            size_t off0 = ((size_t)b0i * Tn + (t + 1)) * H3;
            size_t off1 = ((size_t)b1i * Tn + (t + 1)) * H3;
#pragma unroll
            for (int gate = 0; gate < 3; gate++) {
                pg[gate][0] = GI[off0 + gate * Hn + jjA];
                pg[gate][1] = GI[off0 + gate * Hn + jjB];
                pg[gate][2] = GI[off1 + gate * Hn + jjA];
                pg[gate][3] = GI[off1 + gate * Hn + jjB];
            }
        }
        if (tid == 0) {
            unsigned target = 16u * (unsigned)(t + 1);
            unsigned v;
            do {
                asm volatile("ld.acquire.gpu.global.b32 %0, [%1];"
                             : "=r"(v) : "l"(mybar) : "memory");
                if (v < target) __nanosleep(16);
            } while (v < target);
        }
        __syncthreads();
    }
}

// ---------------- misc -------------------------------------------------------
__global__ void init_kernel(uint2* hs0, unsigned* bar) {
    int i = blockIdx.x * blockDim.x + threadIdx.x;
    if (i < Bn * 256) hs0[i] = make_uint2(0u, 0u);
    if (i < 8) bar[i] = 0u;
}

#define XSP_N   ((size_t)BT * 256)
#define WSP_N   ((size_t)H3 * 256)
#define WOSP_N  ((size_t)DICTn * Qn * 256)
__global__ void presplit_kernel(const float* __restrict__ x,
                                const float* __restrict__ wih,
                                const float* __restrict__ wout,
                                uint2* __restrict__ xsp,
                                uint2* __restrict__ wsp,
                                uint2* __restrict__ wosp)
{
    size_t i = (size_t)blockIdx.x * 256 + threadIdx.x;
    if (i < XSP_N) {
        xsp[i] = splitpk(((const float2*)x)[i]);
    } else if (i < XSP_N + WSP_N) {
        size_t j = i - XSP_N;
        wsp[j] = splitpk(((const float2*)wih)[j]);
    } else {
        size_t j = i - XSP_N - WSP_N;
        if (j < WOSP_N) wosp[j] = splitpk(((const float2*)wout)[j]);
    }
}

__global__ void value_kernel(const float* __restrict__ h2,
                             const float* __restrict__ Wc3,
                             const float* __restrict__ bc3,
                             float* __restrict__ out)
{
    int gw = (blockIdx.x * blockDim.x + threadIdx.x) >> 5;
    int lane = threadIdx.x & 31;
    if (gw >= Bn) return;
    float s = 0.f;
    for (int k = lane; k < Hn; k += 32) s = fmaf(h2[gw * Hn + k], Wc3[k], s);
#pragma unroll
    for (int o = 16; o; o >>= 1) s += __shfl_xor_sync(0xffffffffu, s, o);
    if (lane == 0) out[gw] = s + bc3[0];
}

// fused log-softmax + inline threefry gumbel + categorical sample + one-hot
__global__ __launch_bounds__(256)
void sample_kernel(const float* __restrict__ logits,
                   unsigned k0, unsigned k1,
                   float* __restrict__ out_query,
                   float* __restrict__ out_lp)
{
    __shared__ float red[256];
    __shared__ int   redi[256];
    int row = blockIdx.x;
    int tid = threadIdx.x;
    const float* lg = logits + (size_t)row * DICTn;

    float l[4];
#pragma unroll
    for (int i = 0; i < 4; i++) l[i] = lg[tid + i * 256];

    float mx = fmaxf(fmaxf(l[0], l[1]), fmaxf(l[2], l[3]));
    red[tid] = mx; __syncthreads();
    for (int s = 128; s > 0; s >>= 1) {
        if (tid < s) red[tid] = fmaxf(red[tid], red[tid + s]);
        __syncthreads();
    }
    mx = red[0]; __syncthreads();

    float se = 0.f;
#pragma unroll
    for (int i = 0; i < 4; i++) se += exp_acc(l[i] - mx);
    red[tid] = se; __syncthreads();
    for (int s = 128; s > 0; s >>= 1) {
        if (tid < s) red[tid] += red[tid + s];
        __syncthreads();
    }
    float logZ = mx + log_acc(red[0]); __syncthreads();

    float bv = -1e30f; int bi = 0x7fffffff;
#pragma unroll
    for (int i = 0; i < 4; i++) {
        int idx = tid + i * 256;
        float lp = l[i] - logZ;
        out_lp[(size_t)row * DICTn + idx] = lp;
        unsigned gidx = (unsigned)row * DICTn + idx;
        unsigned o0, o1;
        threefry2x32(k0, k1, 0u, gidx, &o0, &o1);
        unsigned bits = o0 ^ o1;
        float f = __uint_as_float((bits >> 9) | 0x3f800000u) - 1.0f;
        float u = fmaxf(f, 1.17549435e-38f);
        float gum = -log_acc(-log_acc(u));
        float v = lp + gum;
        if (v > bv || (v == bv && idx < bi)) { bv = v; bi = idx; }
    }
    red[tid] = bv; redi[tid] = bi; __syncthreads();
    for (int s = 128; s > 0; s >>= 1) {
        if (tid < s) {
            if (red[tid + s] > red[tid] ||
                (red[tid + s] == red[tid] && redi[tid + s] < redi[tid])) {
                red[tid] = red[tid + s]; redi[tid] = redi[tid + s];
            }
        }
        __syncthreads();
    }
    int win = redi[0];
#pragma unroll
    for (int i = 0; i < 4; i++) {
        int idx = tid + i * 256;
        out_query[(size_t)row * DICTn + idx] = (idx == win) ? 1.f : 0.f;
    }
}

// ---------------- host -------------------------------------------------------
extern "C" void kernel_launch(void* const* d_in, const int* in_sizes, int n_in,
                              void* d_out, int out_size)
{
    const float* x      = (const float*)d_in[0];
    const int*   lens   = (const int*)  d_in[1];
    const float* W_ih   = (const float*)d_in[2];
    const float* W_hh   = (const float*)d_in[3];
    const float* b_ih   = (const float*)d_in[4];
    const float* b_hh   = (const float*)d_in[5];
    const float* W_out  = (const float*)d_in[6];
    const float* b_out  = (const float*)d_in[7];
    const float* Wc1    = (const float*)d_in[8];
    const float* bc1    = (const float*)d_in[9];
    const float* Wc2    = (const float*)d_in[10];
    const float* bc2    = (const float*)d_in[11];
    const float* Wc3    = (const float*)d_in[12];
    const float* bc3    = (const float*)d_in[13];

    float* out_value = (float*)d_out;
    float* out_query = out_value + Bn;
    float* out_lp    = out_query + (size_t)NSAMP;

    float *pGI, *ph, *pc1, *pc2, *plog;
    unsigned* pbar;
    uint2 *phs, *pxsp, *pwsp, *pwosp;
    cudaGetSymbolAddress((void**)&pGI,  g_GI);
    cudaGetSymbolAddress((void**)&ph,   g_h);
    cudaGetSymbolAddress((void**)&pc1,  g_c1);
    cudaGetSymbolAddress((void**)&pc2,  g_c2);
    cudaGetSymbolAddress((void**)&plog, g_logits);
    cudaGetSymbolAddress((void**)&pbar, g_barrier);
    cudaGetSymbolAddress((void**)&phs,  g_hsplit);
    cudaGetSymbolAddress((void**)&pxsp, g_xsp);
    cudaGetSymbolAddress((void**)&pwsp, g_wihsp);
    cudaGetSymbolAddress((void**)&pwosp, g_woutsp);

    const int rec_smem = WS_UNITS * 8 + 4 * 1024 * 8;   // 229376 B
    cudaFuncSetAttribute(gru_persistent,
        cudaFuncAttributeMaxDynamicSharedMemorySize, rec_smem);

    // 1) zero split-h buffer 0 + barriers
    init_kernel<<<(Bn * 256 + 255) / 256, 256>>>(phs, pbar);

    // 2) pre-split x, W_ih, W_out (packed fp16 hi/lo)
    presplit_kernel<<<(unsigned)((XSP_N + WSP_N + WOSP_N + 255) / 256), 256>>>(
        x, W_ih, W_out, pxsp, pwsp, pwosp);

    // 3) GI = x @ W_ih^T + b_ih
    gemm_t<1,1><<<dim3(H3 / 64, BT / 128), 256>>>(pxsp, Dn, pwsp, Dn,
                                                  pGI, H3, Dn, b_ih, 0, lens);

    // 4) persistent recurrence
    gru_persistent<<<NCTA_REC, 512, rec_smem>>>(pGI, W_hh, b_hh, lens,
                                                phs, ph, pbar);
    float* hfin = ph;

    // 5) critic (fp32 h operand; hfinal is fp32)
    gemm_t<0,0><<<dim3(Hn / 64, Bn / 128), 256>>>(hfin, Hn, Wc1, Hn,
                                                  pc1, Hn, Hn, bc1, 1, nullptr);
    gemm_t<0,0><<<dim3(Hn / 64, Bn / 128), 256>>>(pc1, Hn, Wc2, Hn,
                                                  pc2, Hn, Hn, bc2, 1, nullptr);
    value_kernel<<<(Bn * 32 + 255) / 256, 256>>>(pc2, Wc3, bc3, out_value);

    // 6) actor logits (fp32 h x presplit W_out)
    gemm_t<0,1><<<dim3(DICTn * Qn / 64, Bn / 128), 256>>>(
        hfin, Hn, pwosp, Hn, plog, DICTn * Qn, Hn, b_out, 0, nullptr);

    // 7) fused log-softmax + gumbel + sample (skey = fold_in(key(0),1234))
    unsigned s0, s1;
    threefry2x32(0u, 0u, 0u, 1234u, &s0, &s1);
    sample_kernel<<<Bn * Qn, 256>>>(plog, s0, s1, out_query, out_lp);
}